// round 7
// baseline (speedup 1.0000x reference)
#include <cuda_runtime.h>
#include <cstdint>

#define BB   16
#define LL   512
#define CC   256
#define MEL  4096

__device__ float g_h1[BB * LL * CC];          // LN1 out (tf32-rounded) -> conv2 A
__device__ int   g_idx[BB * MEL];             // per-frame token index (-1 invalid)
__device__ float g_wcvt[2 * 3 * CC * CC];     // RNA-rounded weights, both convs

// ---------------------------------------------------------------------------
__device__ __forceinline__ uint32_t f2tf(float f) {
    uint32_t u;
    asm("cvt.rna.tf32.f32 %0, %1;" : "=r"(u) : "f"(f));
    return u;
}
__device__ __forceinline__ float f2tff(float f) { return __uint_as_float(f2tf(f)); }

__device__ __forceinline__ void mma_tf32(float* d, const uint32_t* a, const uint32_t* b) {
    asm volatile(
        "mma.sync.aligned.m16n8k8.row.col.f32.tf32.tf32.f32 "
        "{%0,%1,%2,%3}, {%4,%5,%6,%7}, {%8,%9}, {%0,%1,%2,%3};"
        : "+f"(d[0]), "+f"(d[1]), "+f"(d[2]), "+f"(d[3])
        : "r"(a[0]), "r"(a[1]), "r"(a[2]), "r"(a[3]), "r"(b[0]), "r"(b[1]));
}
__device__ __forceinline__ uint32_t smem_u32(const void* p) {
    uint32_t a;
    asm("{ .reg .u64 t; cvta.to.shared.u64 t, %1; cvt.u32.u64 %0, t; }"
        : "=r"(a) : "l"(p));
    return a;
}
#define CP_ASYNC16(dst, src) \
    asm volatile("cp.async.ca.shared.global [%0], [%1], 16;" :: "r"(dst), "l"(src))
#define CP_COMMIT() asm volatile("cp.async.commit_group;" ::: "memory")
#define CP_WAIT1()  asm volatile("cp.async.wait_group 1;" ::: "memory")
#define CP_WAIT0()  asm volatile("cp.async.wait_group 0;" ::: "memory")

#define SA_STR 264
#define SB_STR 264
#define SA_FLOATS (66 * SA_STR)
#define SB_FLOATS (64 * SB_STR)
#define SMEM_FLOATS (SA_FLOATS + 2 * SB_FLOATS)
#define SMEM_BYTES  (SMEM_FLOATS * 4)    // 204864

#define NSLOT 10                          // 6 MMA n-warps + 4 FFMA warps

// ---------------------------------------------------------------------------
// Prep: float4-vectorized weight RNA pre-round + cumsum/frame-idx
// ---------------------------------------------------------------------------
__global__ void __launch_bounds__(512) prep_kernel(const float* __restrict__ w1,
                                                   const float* __restrict__ w2,
                                                   const int* __restrict__ dur)
{
    if (blockIdx.x < 192) {
        int i = blockIdx.x * 512 + threadIdx.x;        // 0..98303 float4 slots
        const int HALF = 49152;                        // float4 per conv
        const float4* src = (i < HALF) ? (const float4*)w1 : (const float4*)w2;
        int j = (i < HALF) ? i : i - HALF;
        float4 v = src[j];
        v.x = f2tff(v.x); v.y = f2tff(v.y); v.z = f2tff(v.z); v.w = f2tff(v.w);
        ((float4*)g_wcvt)[i] = v;
        return;
    }
    __shared__ int s[LL];
    int b = blockIdx.x - 192, tid = threadIdx.x;
    s[tid] = dur[b * LL + tid];
    __syncthreads();
    for (int off = 1; off < LL; off <<= 1) {
        int v = (tid >= off) ? s[tid - off] : 0;
        __syncthreads();
        s[tid] += v;
        __syncthreads();
    }
    int total = s[LL - 1];
#pragma unroll
    for (int r = 0; r < 8; r++) {
        int t = tid + r * 512;
        int lo = 0, hi = LL;
        while (lo < hi) {
            int mid = (lo + hi) >> 1;
            if (s[mid] <= t) lo = mid + 1; else hi = mid;
        }
        g_idx[b * MEL + t] = (t < total) ? min(lo, LL - 1) : -1;
    }
}

// ---------------------------------------------------------------------------
// Fused conv1d(K=3,SAME)+bias+ReLU+LN [+linear head if FINAL]
// CTA = [64 l x 256 f], 512 threads / 16 warps.
//   warps 0..11 : tf32 MMA, cols 0..191  (nw=warp>>1, mh=warp&1, 32x32 tiles)
//   warps 12..15: fp32 FFMA, cols 192..255 (16 cols/warp, 8x4 thread tiles)
// A resident in smem; B cp.async double-buffered. Conv1 streams regulate out.
// ---------------------------------------------------------------------------
template <bool FINAL>
__global__ void __launch_bounds__(512, 1)
conv_mma_kernel(const float* __restrict__ xin,
                const float* __restrict__ bias,
                const float* __restrict__ gamma,
                const float* __restrict__ beta,
                const float* __restrict__ linw,
                const float* __restrict__ linb,
                float* __restrict__ predout,
                float* __restrict__ regout)
{
    extern __shared__ __align__(16) float smem[];
    float* sA = smem;
    float* sB[2] = { smem + SA_FLOATS, smem + SA_FLOATS + SB_FLOATS };
    const uint32_t sb_u32[2] = { smem_u32(sB[0]), smem_u32(sB[1]) };

    const int tid  = threadIdx.x;
    const int warp = tid >> 5, lane = tid & 31;
    const int g = lane >> 2, q = lane & 3;
    const bool isF = (warp >= 12);                 // FFMA warp?
    // MMA-warp tiling
    const int mh = warp & 1;
    const int nw = warp >> 1;                      // 0..5 for MMA warps
    const int n0 = nw * 32;
    const int m0 = mh * 32;
    // FFMA-warp tiling
    const int fw  = warp & 3;                      // 0..3 (for warps 12..15)
    const int c0f = 192 + fw * 16;
    const int cx  = lane & 3;                      // col group (4 cols)
    const int b  = blockIdx.y;
    const int l0 = blockIdx.x * 64;
    const int CONV = FINAL ? 1 : 0;
    const float* inb = (FINAL ? (const float*)g_h1 : xin) + (size_t)b * LL * CC;
    const float* wbase = g_wcvt + (size_t)CONV * 3 * CC * CC;

    auto stageB = [&](int it, int buf) {
        const int k = it >> 2, c0 = (it & 3) * 64;
        const float* src = wbase + ((size_t)(k * CC + c0)) * CC;
#pragma unroll
        for (int i = 0; i < 8; i++) {
            int idx = tid + i * 512;
            int c = idx >> 6, f4 = idx & 63;
            CP_ASYNC16(sb_u32[buf] + (uint32_t)(c * SB_STR + f4 * 4) * 4,
                       src + (size_t)c * CC + f4 * 4);
        }
        CP_COMMIT();
    };
    stageB(0, 0);
    stageB(1, 1);

#pragma unroll 3
    for (int i = 0; i < 9; i++) {
        int idx = tid + i * 512;
        if (idx < 66 * 64) {
            int sr = idx >> 6, f4 = idx & 63;
            int grow = l0 + sr - 1;
            float4 v = make_float4(0.f, 0.f, 0.f, 0.f);
            if (grow >= 0 && grow < LL)
                v = *(const float4*)(inb + (size_t)grow * CC + f4 * 4);
            if (!FINAL) { v.x = f2tff(v.x); v.y = f2tff(v.y);
                          v.z = f2tff(v.z); v.w = f2tff(v.w); }
            *(float4*)(sA + sr * SA_STR + f4 * 4) = v;
        }
    }

    float acc[2][4][4];                            // MMA accumulators
    float accf[8][4];                              // FFMA accumulators
#pragma unroll
    for (int mt = 0; mt < 2; mt++)
#pragma unroll
        for (int nt = 0; nt < 4; nt++)
#pragma unroll
            for (int r = 0; r < 4; r++) acc[mt][nt][r] = 0.f;
#pragma unroll
    for (int i = 0; i < 8; i++)
#pragma unroll
        for (int j = 0; j < 4; j++) accf[i][j] = 0.f;

    for (int it = 0; it < 12; it++) {
        const int ktap = it >> 2, c0 = (it & 3) * 64;
        const int buf = it & 1;
        if (it < 11) CP_WAIT1(); else CP_WAIT0();
        __syncthreads();

        const float* bp = sB[buf];
        if (!isF) {
            // ---------------- tensor path (cols 0..191) ----------------
            const float* ap = sA + (ktap + m0 + g) * SA_STR + c0 + q;
#pragma unroll
            for (int ks = 0; ks < 8; ks++) {
                uint32_t af[2][4], bf[4][2];
#pragma unroll
                for (int mt = 0; mt < 2; mt++) {
                    const float* a0 = ap + mt * (16 * SA_STR) + ks * 8;
                    af[mt][0] = __float_as_uint(a0[0]);
                    af[mt][1] = __float_as_uint(a0[8 * SA_STR]);
                    af[mt][2] = __float_as_uint(a0[4]);
                    af[mt][3] = __float_as_uint(a0[8 * SA_STR + 4]);
                }
#pragma unroll
                for (int nt = 0; nt < 4; nt++) {
                    bf[nt][0] = __float_as_uint(bp[(ks * 8 + q) * SB_STR + n0 + nt * 8 + g]);
                    bf[nt][1] = __float_as_uint(bp[(ks * 8 + q + 4) * SB_STR + n0 + nt * 8 + g]);
                }
#pragma unroll
                for (int mt = 0; mt < 2; mt++)
#pragma unroll
                    for (int nt = 0; nt < 4; nt++)
                        mma_tf32(acc[mt][nt], af[mt], bf[nt]);
            }
        } else {
            // ---------------- FFMA path (cols 192..255) ----------------
            const float* ap = sA + (ktap + g) * SA_STR + c0;
            const float* bq = bp + c0f + cx * 4;
#pragma unroll
            for (int k4 = 0; k4 < 16; k4++) {
                float4 av[8], bv[4];
#pragma unroll
                for (int i = 0; i < 8; i++)
                    av[i] = *(const float4*)(ap + i * (8 * SA_STR) + k4 * 4);
#pragma unroll
                for (int kk = 0; kk < 4; kk++)
                    bv[kk] = *(const float4*)(bq + (k4 * 4 + kk) * SB_STR);
#pragma unroll
                for (int i = 0; i < 8; i++) {
                    accf[i][0] += av[i].x * bv[0].x + av[i].y * bv[1].x
                                + av[i].z * bv[2].x + av[i].w * bv[3].x;
                    accf[i][1] += av[i].x * bv[0].y + av[i].y * bv[1].y
                                + av[i].z * bv[2].y + av[i].w * bv[3].y;
                    accf[i][2] += av[i].x * bv[0].z + av[i].y * bv[1].z
                                + av[i].z * bv[2].z + av[i].w * bv[3].z;
                    accf[i][3] += av[i].x * bv[0].w + av[i].y * bv[1].w
                                + av[i].z * bv[2].w + av[i].w * bv[3].w;
                }
            }
        }
        __syncthreads();
        if (it + 2 < 12) stageB(it + 2, buf);

        // ---- interleaved length regulation (conv1 only, all threads) ----
        if (!FINAL) {
            int ix[6];
            float4 vv[6];
#pragma unroll
            for (int u = 0; u < 6; u++) {
                int s = it * 6 + u;
                ix[u] = -1;
                if (s < 64)
                    ix[u] = g_idx[b * MEL + blockIdx.x * 512 + ((tid + s * 512) >> 6)];
            }
#pragma unroll
            for (int u = 0; u < 6; u++) {
                vv[u] = make_float4(0.f, 0.f, 0.f, 0.f);
                if (ix[u] >= 0) {
                    int s = it * 6 + u;
                    int c4 = (tid + s * 512) & 63;
                    vv[u] = *(const float4*)(xin + ((size_t)b * LL + ix[u]) * CC + c4 * 4);
                }
            }
#pragma unroll
            for (int u = 0; u < 6; u++) {
                int s = it * 6 + u;
                if (s < 64) {
                    int j = tid + s * 512;
                    int fr = j >> 6, c4 = j & 63;
                    *(float4*)(regout + ((size_t)b * MEL + blockIdx.x * 512 + fr) * CC + c4 * 4) = vv[u];
                }
            }
        }
    }
    __syncthreads();

    // ---- epilogue: bias + ReLU + LN (fused), optional linear head ----
    float2* red   = (float2*)sA;                   // [64 rows][NSLOT]
    float2* stats = (float2*)sA + 64 * NSLOT;      // [64]
    float*  dred  = sA + 2048;                     // [64 rows][NSLOT]

    float v[2][2][8];                              // MMA post-ReLU values
    float vf[8][4];                                // FFMA post-ReLU values
    float bi[8], ga[8], be[8], lw[8];

    if (!isF) {
#pragma unroll
        for (int nt = 0; nt < 4; nt++)
#pragma unroll
            for (int j = 0; j < 2; j++) {
                int c = n0 + nt * 8 + 2 * q + j;
                bi[nt * 2 + j] = __ldg(bias + c);
                ga[nt * 2 + j] = __ldg(gamma + c);
                be[nt * 2 + j] = __ldg(beta + c);
                if (FINAL) lw[nt * 2 + j] = __ldg(linw + c);
            }
#pragma unroll
        for (int mt = 0; mt < 2; mt++)
#pragma unroll
            for (int h = 0; h < 2; h++) {
                float s = 0.f, s2 = 0.f;
#pragma unroll
                for (int nt = 0; nt < 4; nt++)
#pragma unroll
                    for (int j = 0; j < 2; j++) {
                        float x = acc[mt][nt][h * 2 + j] + bi[nt * 2 + j];
                        x = fmaxf(x, 0.f);
                        v[mt][h][nt * 2 + j] = x;
                        s += x; s2 += x * x;
                    }
                s  += __shfl_xor_sync(0xffffffffu, s, 1);
                s2 += __shfl_xor_sync(0xffffffffu, s2, 1);
                s  += __shfl_xor_sync(0xffffffffu, s, 2);
                s2 += __shfl_xor_sync(0xffffffffu, s2, 2);
                if (q == 0)
                    red[(m0 + mt * 16 + g + 8 * h) * NSLOT + nw] = make_float2(s, s2);
            }
    } else {
#pragma unroll
        for (int j = 0; j < 4; j++) {
            int c = c0f + cx * 4 + j;
            bi[j] = __ldg(bias + c);
            ga[j] = __ldg(gamma + c);
            be[j] = __ldg(beta + c);
            if (FINAL) lw[j] = __ldg(linw + c);
        }
#pragma unroll
        for (int i = 0; i < 8; i++) {
            float s = 0.f, s2 = 0.f;
#pragma unroll
            for (int j = 0; j < 4; j++) {
                float x = fmaxf(accf[i][j] + bi[j], 0.f);
                vf[i][j] = x;
                s += x; s2 += x * x;
            }
            s  += __shfl_xor_sync(0xffffffffu, s, 1);
            s2 += __shfl_xor_sync(0xffffffffu, s2, 1);
            s  += __shfl_xor_sync(0xffffffffu, s, 2);
            s2 += __shfl_xor_sync(0xffffffffu, s2, 2);
            if (cx == 0)
                red[(g + 8 * i) * NSLOT + 6 + fw] = make_float2(s, s2);
        }
    }
    __syncthreads();
    if (tid < 64) {
        float s = 0.f, s2 = 0.f;
#pragma unroll
        for (int wv = 0; wv < NSLOT; wv++) {
            float2 p = red[tid * NSLOT + wv];
            s += p.x; s2 += p.y;
        }
        float mu = s * (1.f / 256.f);
        float var = s2 * (1.f / 256.f) - mu * mu;
        stats[tid] = make_float2(mu, rsqrtf(var + 1e-5f));
    }
    __syncthreads();

    if (!FINAL) {
        if (!isF) {
#pragma unroll
            for (int mt = 0; mt < 2; mt++)
#pragma unroll
                for (int h = 0; h < 2; h++) {
                    int r = m0 + mt * 16 + g + 8 * h;
                    float2 st = stats[r];
                    float* orow = g_h1 + ((size_t)b * LL + l0 + r) * CC;
#pragma unroll
                    for (int nt = 0; nt < 4; nt++) {
                        float2 o;
                        o.x = f2tff((v[mt][h][nt * 2]     - st.x) * st.y * ga[nt * 2]     + be[nt * 2]);
                        o.y = f2tff((v[mt][h][nt * 2 + 1] - st.x) * st.y * ga[nt * 2 + 1] + be[nt * 2 + 1]);
                        *(float2*)(orow + n0 + nt * 8 + 2 * q) = o;
                    }
                }
        } else {
#pragma unroll
            for (int i = 0; i < 8; i++) {
                int r = g + 8 * i;
                float2 st = stats[r];
                float4 o;
                o.x = f2tff((vf[i][0] - st.x) * st.y * ga[0] + be[0]);
                o.y = f2tff((vf[i][1] - st.x) * st.y * ga[1] + be[1]);
                o.z = f2tff((vf[i][2] - st.x) * st.y * ga[2] + be[2]);
                o.w = f2tff((vf[i][3] - st.x) * st.y * ga[3] + be[3]);
                *(float4*)(g_h1 + ((size_t)b * LL + l0 + r) * CC + c0f + cx * 4) = o;
            }
        }
    } else {
        if (!isF) {
#pragma unroll
            for (int mt = 0; mt < 2; mt++)
#pragma unroll
                for (int h = 0; h < 2; h++) {
                    int r = m0 + mt * 16 + g + 8 * h;
                    float2 st = stats[r];
                    float d = 0.f;
#pragma unroll
                    for (int p = 0; p < 8; p++)
                        d += ((v[mt][h][p] - st.x) * st.y * ga[p] + be[p]) * lw[p];
                    d += __shfl_xor_sync(0xffffffffu, d, 1);
                    d += __shfl_xor_sync(0xffffffffu, d, 2);
                    if (q == 0) dred[r * NSLOT + nw] = d;
                }
        } else {
#pragma unroll
            for (int i = 0; i < 8; i++) {
                int r = g + 8 * i;
                float2 st = stats[r];
                float d = 0.f;
#pragma unroll
                for (int j = 0; j < 4; j++)
                    d += ((vf[i][j] - st.x) * st.y * ga[j] + be[j]) * lw[j];
                d += __shfl_xor_sync(0xffffffffu, d, 1);
                d += __shfl_xor_sync(0xffffffffu, d, 2);
                if (cx == 0) dred[r * NSLOT + 6 + fw] = d;
            }
        }
        __syncthreads();
        if (tid < 64) {
            float d = 0.f;
#pragma unroll
            for (int wv = 0; wv < NSLOT; wv++) d += dred[tid * NSLOT + wv];
            predout[b * LL + l0 + tid] = d + __ldg(linb);
        }
    }
}

// ---------------------------------------------------------------------------
extern "C" void kernel_launch(void* const* d_in, const int* in_sizes, int n_in,
                              void* d_out, int out_size)
{
    const float* x    = (const float*)d_in[0];
    const int*   dur  = (const int*)d_in[1];
    const float* c1w  = (const float*)d_in[2];
    const float* c1b  = (const float*)d_in[3];
    const float* ln1g = (const float*)d_in[4];
    const float* ln1b = (const float*)d_in[5];
    const float* c2w  = (const float*)d_in[6];
    const float* c2b  = (const float*)d_in[7];
    const float* ln2g = (const float*)d_in[8];
    const float* ln2b = (const float*)d_in[9];
    const float* linw = (const float*)d_in[10];
    const float* linb = (const float*)d_in[11];

    float* out  = (float*)d_out;
    float* pred = out + (size_t)BB * MEL * CC;

    cudaFuncSetAttribute(conv_mma_kernel<false>,
                         cudaFuncAttributeMaxDynamicSharedMemorySize, SMEM_BYTES);
    cudaFuncSetAttribute(conv_mma_kernel<true>,
                         cudaFuncAttributeMaxDynamicSharedMemorySize, SMEM_BYTES);

    prep_kernel<<<192 + BB, 512>>>(c1w, c2w, dur);

    dim3 cgrid(LL / 64, BB);
    conv_mma_kernel<false><<<cgrid, 512, SMEM_BYTES>>>(x, c1b, ln1g, ln1b,
                                                       nullptr, nullptr, nullptr, out);
    conv_mma_kernel<true><<<cgrid, 512, SMEM_BYTES>>>(x, c2b, ln2g, ln2b,
                                                      linw, linb, pred, nullptr);
}

// round 8
// speedup vs baseline: 2.6994x; 2.6994x over previous
#include <cuda_runtime.h>
#include <cuda_fp16.h>
#include <cstdint>

#define BB   16
#define LL   512
#define CC   256
#define MEL  4096

// ---------------------------------------------------------------------------
// Scratch (__device__ globals — allocations are forbidden)
// ---------------------------------------------------------------------------
__device__ uint32_t g_h1pk[BB * LL * 128];        // h1 as packed half2 [b][l][kpair]
__device__ int      g_idx[BB * MEL];              // per-frame token index
__device__ uint32_t g_wpk[2 * 3 * 128 * 256];     // weights packed half2 [conv][tap][kpair][n]

// ---------------------------------------------------------------------------
__device__ __forceinline__ uint32_t pack_h2(float a, float b) {
    __half2 h = __floats2half2_rn(a, b);
    return *reinterpret_cast<uint32_t*>(&h);
}

__device__ __forceinline__ void mma_f16(float* d, const uint32_t* a, const uint32_t* b) {
    asm volatile(
        "mma.sync.aligned.m16n8k16.row.col.f32.f16.f16.f32 "
        "{%0,%1,%2,%3}, {%4,%5,%6,%7}, {%8,%9}, {%0,%1,%2,%3};"
        : "+f"(d[0]), "+f"(d[1]), "+f"(d[2]), "+f"(d[3])
        : "r"(a[0]), "r"(a[1]), "r"(a[2]), "r"(a[3]), "r"(b[0]), "r"(b[1]));
}
__device__ __forceinline__ uint32_t smem_u32(const void* p) {
    uint32_t a;
    asm("{ .reg .u64 t; cvta.to.shared.u64 t, %1; cvt.u32.u64 %0, t; }"
        : "=r"(a) : "l"(p));
    return a;
}
#define CP_ASYNC16(dst, src) \
    asm volatile("cp.async.ca.shared.global [%0], [%1], 16;" :: "r"(dst), "l"(src))
#define CP_COMMIT() asm volatile("cp.async.commit_group;" ::: "memory")
#define CP_WAIT1()  asm volatile("cp.async.wait_group 1;" ::: "memory")
#define CP_WAIT0()  asm volatile("cp.async.wait_group 0;" ::: "memory")

// smem geometry (uint32 units).
// A: [66 rows][132]  (128 kpairs + pad; 132 % 32 = 4  -> frag bank = 4g+q, distinct)
// B: [32 kpairs][264] (256 n + pad;   264 % 32 = 8  -> frag bank = 8q+g, distinct)
#define A_STR 132
#define B_STR 264
#define A_U32 (66 * A_STR)               // 8712
#define B_U32 (32 * B_STR)               // 8448
#define SMEM_BYTES ((A_U32 + 2 * B_U32) * 4)   // 102432

// ---------------------------------------------------------------------------
// Prep: weight fp16 pack [conv][tap][kpair][n] + cumsum/frame-idx
// ---------------------------------------------------------------------------
__global__ void __launch_bounds__(512) prep_kernel(const float* __restrict__ w1,
                                                   const float* __restrict__ w2,
                                                   const int* __restrict__ dur)
{
    if (blockIdx.x < 192) {
        int idx = blockIdx.x * 512 + threadIdx.x;      // 0..98303
        int tap = idx >> 15;
        int kp  = (idx >> 8) & 127;
        int n   = idx & 255;
        const float* s1 = w1 + (size_t)tap * 65536 + (size_t)kp * 512 + n;
        const float* s2 = w2 + (size_t)tap * 65536 + (size_t)kp * 512 + n;
        g_wpk[idx]         = pack_h2(s1[0], s1[256]);
        g_wpk[idx + 98304] = pack_h2(s2[0], s2[256]);
        return;
    }
    __shared__ int s[LL];
    int b = blockIdx.x - 192, tid = threadIdx.x;
    s[tid] = dur[b * LL + tid];
    __syncthreads();
    for (int off = 1; off < LL; off <<= 1) {
        int v = (tid >= off) ? s[tid - off] : 0;
        __syncthreads();
        s[tid] += v;
        __syncthreads();
    }
    int total = s[LL - 1];
#pragma unroll
    for (int r = 0; r < 8; r++) {
        int t = tid + r * 512;
        int lo = 0, hi = LL;
        while (lo < hi) {
            int mid = (lo + hi) >> 1;
            if (s[mid] <= t) lo = mid + 1; else hi = mid;
        }
        g_idx[b * MEL + t] = (t < total) ? min(lo, LL - 1) : -1;
    }
}

// ---------------------------------------------------------------------------
// Fused conv1d(K=3,SAME)+bias+ReLU+LN [+linear head if FINAL], fp16 MMA.
// CTA = [64 l x 256 f], 256 threads / 8 warps, warp tile 64x32.
// A resident (half2, [row][kpair]); B cp.async double-buffered.
// Conv1 streams the length-regulated output; conv1 stores h1 packed fp16.
// ---------------------------------------------------------------------------
template <bool FINAL>
__global__ void __launch_bounds__(256, 1)
conv_mma_kernel(const float* __restrict__ xin,
                const float* __restrict__ bias,
                const float* __restrict__ gamma,
                const float* __restrict__ beta,
                const float* __restrict__ linw,
                const float* __restrict__ linb,
                float* __restrict__ predout,
                float* __restrict__ regout)
{
    extern __shared__ __align__(16) uint32_t smu[];
    uint32_t* sA2 = smu;
    uint32_t* sB[2] = { smu + A_U32, smu + A_U32 + B_U32 };
    const uint32_t sa_u32 = smem_u32(sA2);
    const uint32_t sb_u32[2] = { smem_u32(sB[0]), smem_u32(sB[1]) };

    const int tid  = threadIdx.x;
    const int warp = tid >> 5, lane = tid & 31;
    const int g = lane >> 2, q = lane & 3;
    const int n0 = warp * 32;
    const int b  = blockIdx.y;
    const int l0 = blockIdx.x * 64;
    const int CONV = FINAL ? 1 : 0;

    auto stageB = [&](int it, int buf) {
        const uint32_t* src = g_wpk + ((size_t)(CONV * 3 + (it >> 2)) * 128 + (it & 3) * 32) * 256;
#pragma unroll
        for (int i = 0; i < 8; i++) {
            int idx = tid + i * 256;               // 0..2047 (16B segs)
            int c = idx >> 6, n4 = idx & 63;
            CP_ASYNC16(sb_u32[buf] + (uint32_t)(c * B_STR + n4 * 4) * 4,
                       src + (size_t)c * 256 + n4 * 4);
        }
        CP_COMMIT();
    };

    stageB(0, 0);
    if (FINAL) {
        // A from packed h1: straight cp.async rows, zero-fill OOB
        const uint32_t* h1b = g_h1pk + (size_t)b * LL * 128;
#pragma unroll
        for (int i = 0; i < 9; i++) {
            int idx = tid + i * 256;               // need 66*32 = 2112 segs
            if (idx < 66 * 32) {
                int row = idx >> 5, seg = idx & 31;
                int grow = l0 + row - 1;
                if (grow >= 0 && grow < LL)
                    CP_ASYNC16(sa_u32 + (uint32_t)(row * A_STR + seg * 4) * 4,
                               h1b + (size_t)grow * 128 + seg * 4);
                else
                    *(float4*)(sA2 + row * A_STR + seg * 4) =
                        make_float4(0.f, 0.f, 0.f, 0.f);
            }
        }
        CP_COMMIT();
    }
    stageB(1, 1);
    if (!FINAL) {
        // A from fp32 x: convert+pack, transposed store (STS.64, coalesced)
        const float* inb = xin + (size_t)b * LL * CC;
#pragma unroll 4
        for (int i = 0; i < 17; i++) {
            int idx = tid + i * 256;               // need 66*64 = 4224
            if (idx < 66 * 64) {
                int c4 = idx & 63, row = idx >> 6;
                int grow = l0 + row - 1;
                float4 v = make_float4(0.f, 0.f, 0.f, 0.f);
                if (grow >= 0 && grow < LL)
                    v = *(const float4*)(inb + (size_t)grow * CC + c4 * 4);
                uint32_t h01 = pack_h2(v.x, v.y);
                uint32_t h23 = pack_h2(v.z, v.w);
                unsigned long long dd = ((unsigned long long)h23 << 32) | h01;
                *(unsigned long long*)(sA2 + row * A_STR + c4 * 2) = dd;
            }
        }
    }

    float acc[4][4][4];
#pragma unroll
    for (int mt = 0; mt < 4; mt++)
#pragma unroll
        for (int nt = 0; nt < 4; nt++)
#pragma unroll
            for (int r = 0; r < 4; r++) acc[mt][nt][r] = 0.f;

    for (int it = 0; it < 12; it++) {
        const int ktap = it >> 2, chunk = it & 3;
        const int buf = it & 1;
        if (it < 11) CP_WAIT1(); else CP_WAIT0();
        __syncthreads();

        const uint32_t* ab = sA2 + (ktap + g) * A_STR + chunk * 32 + q;
        const uint32_t* bb = sB[buf] + n0 + g;
#pragma unroll
        for (int ks = 0; ks < 4; ks++) {
            uint32_t af[4][4], bf[4][2];
#pragma unroll
            for (int mt = 0; mt < 4; mt++) {
                const uint32_t* ap = ab + mt * (16 * A_STR) + ks * 8;
                af[mt][0] = ap[0];
                af[mt][1] = ap[8 * A_STR];
                af[mt][2] = ap[4];
                af[mt][3] = ap[8 * A_STR + 4];
            }
#pragma unroll
            for (int nt = 0; nt < 4; nt++) {
                bf[nt][0] = bb[(ks * 8 + q) * B_STR + nt * 8];
                bf[nt][1] = bb[(ks * 8 + q + 4) * B_STR + nt * 8];
            }
#pragma unroll
            for (int mt = 0; mt < 4; mt++)
#pragma unroll
                for (int nt = 0; nt < 4; nt++)
                    mma_f16(acc[mt][nt], af[mt], bf[nt]);
        }
        __syncthreads();
        if (it + 2 < 12) stageB(it + 2, buf);

        // ---- interleaved length regulation (conv1 only) ----
        if (!FINAL) {
            int ix[11];
            float4 vv[11];
#pragma unroll
            for (int u = 0; u < 11; u++) {
                int s = it * 11 + u;
                ix[u] = -1;
                if (s < 128)
                    ix[u] = g_idx[b * MEL + blockIdx.x * 512 + ((tid + s * 256) >> 6)];
            }
#pragma unroll
            for (int u = 0; u < 11; u++) {
                vv[u] = make_float4(0.f, 0.f, 0.f, 0.f);
                if (ix[u] >= 0) {
                    int s = it * 11 + u;
                    int c4 = (tid + s * 256) & 63;
                    vv[u] = *(const float4*)(xin + ((size_t)b * LL + ix[u]) * CC + c4 * 4);
                }
            }
#pragma unroll
            for (int u = 0; u < 11; u++) {
                int s = it * 11 + u;
                if (s < 128) {
                    int j = tid + s * 256;
                    int fr = j >> 6, c4 = j & 63;
                    *(float4*)(regout + ((size_t)b * MEL + blockIdx.x * 512 + fr) * CC + c4 * 4) = vv[u];
                }
            }
        }
    }
    __syncthreads();

    // ---- epilogue: bias + ReLU + LN (fused), optional linear head ----
    float bi[8], ga[8], be[8], lw[8];
#pragma unroll
    for (int nt = 0; nt < 4; nt++)
#pragma unroll
        for (int j = 0; j < 2; j++) {
            int c = n0 + nt * 8 + 2 * q + j;
            bi[nt * 2 + j] = __ldg(bias + c);
            ga[nt * 2 + j] = __ldg(gamma + c);
            be[nt * 2 + j] = __ldg(beta + c);
            if (FINAL) lw[nt * 2 + j] = __ldg(linw + c);
        }

    float v[4][2][8];
    float2* red   = (float2*)sA2;                  // [64 rows][8 warps]
    float2* stats = red + 512;                     // [64]
    float*  dred  = (float*)sA2 + 2048;            // [64 rows][8 warps]

#pragma unroll
    for (int mt = 0; mt < 4; mt++)
#pragma unroll
        for (int h = 0; h < 2; h++) {
            float s = 0.f, s2 = 0.f;
#pragma unroll
            for (int nt = 0; nt < 4; nt++)
#pragma unroll
                for (int j = 0; j < 2; j++) {
                    float x = acc[mt][nt][h * 2 + j] + bi[nt * 2 + j];
                    x = fmaxf(x, 0.f);
                    v[mt][h][nt * 2 + j] = x;
                    s += x; s2 += x * x;
                }
            s  += __shfl_xor_sync(0xffffffffu, s, 1);
            s2 += __shfl_xor_sync(0xffffffffu, s2, 1);
            s  += __shfl_xor_sync(0xffffffffu, s, 2);
            s2 += __shfl_xor_sync(0xffffffffu, s2, 2);
            if (q == 0)
                red[(mt * 16 + g + 8 * h) * 8 + warp] = make_float2(s, s2);
        }
    __syncthreads();
    if (tid < 64) {
        float s = 0.f, s2 = 0.f;
#pragma unroll
        for (int wv = 0; wv < 8; wv++) {
            float2 p = red[tid * 8 + wv];
            s += p.x; s2 += p.y;
        }
        float mu = s * (1.f / 256.f);
        float var = s2 * (1.f / 256.f) - mu * mu;
        stats[tid] = make_float2(mu, rsqrtf(var + 1e-5f));
    }
    __syncthreads();

    if (!FINAL) {
        // store h1 as packed fp16 (conv2 consumes directly)
#pragma unroll
        for (int mt = 0; mt < 4; mt++)
#pragma unroll
            for (int h = 0; h < 2; h++) {
                int r = mt * 16 + g + 8 * h;
                float2 st = stats[r];
                uint32_t* orow = g_h1pk + ((size_t)b * LL + l0 + r) * 128 + warp * 16;
#pragma unroll
                for (int nt = 0; nt < 4; nt++) {
                    float ox = (v[mt][h][nt * 2]     - st.x) * st.y * ga[nt * 2]     + be[nt * 2];
                    float oy = (v[mt][h][nt * 2 + 1] - st.x) * st.y * ga[nt * 2 + 1] + be[nt * 2 + 1];
                    orow[nt * 4 + q] = pack_h2(ox, oy);
                }
            }
    } else {
#pragma unroll
        for (int mt = 0; mt < 4; mt++)
#pragma unroll
            for (int h = 0; h < 2; h++) {
                int r = mt * 16 + g + 8 * h;
                float2 st = stats[r];
                float d = 0.f;
#pragma unroll
                for (int p = 0; p < 8; p++)
                    d += ((v[mt][h][p] - st.x) * st.y * ga[p] + be[p]) * lw[p];
                d += __shfl_xor_sync(0xffffffffu, d, 1);
                d += __shfl_xor_sync(0xffffffffu, d, 2);
                if (q == 0) dred[r * 8 + warp] = d;
            }
        __syncthreads();
        if (tid < 64) {
            float d = 0.f;
#pragma unroll
            for (int wv = 0; wv < 8; wv++) d += dred[tid * 8 + wv];
            predout[b * LL + l0 + tid] = d + __ldg(linb);
        }
    }
}

// ---------------------------------------------------------------------------
extern "C" void kernel_launch(void* const* d_in, const int* in_sizes, int n_in,
                              void* d_out, int out_size)
{
    const float* x    = (const float*)d_in[0];
    const int*   dur  = (const int*)d_in[1];
    const float* c1w  = (const float*)d_in[2];
    const float* c1b  = (const float*)d_in[3];
    const float* ln1g = (const float*)d_in[4];
    const float* ln1b = (const float*)d_in[5];
    const float* c2w  = (const float*)d_in[6];
    const float* c2b  = (const float*)d_in[7];
    const float* ln2g = (const float*)d_in[8];
    const float* ln2b = (const float*)d_in[9];
    const float* linw = (const float*)d_in[10];
    const float* linb = (const float*)d_in[11];

    float* out  = (float*)d_out;
    float* pred = out + (size_t)BB * MEL * CC;

    cudaFuncSetAttribute(conv_mma_kernel<false>,
                         cudaFuncAttributeMaxDynamicSharedMemorySize, SMEM_BYTES);
    cudaFuncSetAttribute(conv_mma_kernel<true>,
                         cudaFuncAttributeMaxDynamicSharedMemorySize, SMEM_BYTES);

    prep_kernel<<<192 + BB, 512>>>(c1w, c2w, dur);

    dim3 cgrid(LL / 64, BB);
    conv_mma_kernel<false><<<cgrid, 256, SMEM_BYTES>>>(x, c1b, ln1g, ln1b,
                                                       nullptr, nullptr, nullptr, out);
    conv_mma_kernel<true><<<cgrid, 256, SMEM_BYTES>>>(x, c2b, ln2g, ln2b,
                                                      linw, linb, pred, nullptr);
}

// round 9
// speedup vs baseline: 2.7784x; 1.0293x over previous
#include <cuda_runtime.h>
#include <cuda_fp16.h>
#include <cstdint>

#define BB   16
#define LL   512
#define CC   256
#define MEL  4096

// ---------------------------------------------------------------------------
// Scratch (__device__ globals — allocations are forbidden)
// ---------------------------------------------------------------------------
__device__ uint32_t g_h1pk[BB * LL * 128];        // h1 as packed half2 [b][l][kpair]
__device__ int      g_idx[BB * MEL];              // per-frame token index
__device__ uint32_t g_wpk[2 * 3 * 128 * 256];     // weights packed half2 [conv][tap][kpair][n]

// ---------------------------------------------------------------------------
__device__ __forceinline__ uint32_t pack_h2(float a, float b) {
    __half2 h = __floats2half2_rn(a, b);
    return *reinterpret_cast<uint32_t*>(&h);
}

__device__ __forceinline__ void mma_f16(float* d, const uint32_t* a, const uint32_t* b) {
    asm volatile(
        "mma.sync.aligned.m16n8k16.row.col.f32.f16.f16.f32 "
        "{%0,%1,%2,%3}, {%4,%5,%6,%7}, {%8,%9}, {%0,%1,%2,%3};"
        : "+f"(d[0]), "+f"(d[1]), "+f"(d[2]), "+f"(d[3])
        : "r"(a[0]), "r"(a[1]), "r"(a[2]), "r"(a[3]), "r"(b[0]), "r"(b[1]));
}
__device__ __forceinline__ uint32_t smem_u32(const void* p) {
    uint32_t a;
    asm("{ .reg .u64 t; cvta.to.shared.u64 t, %1; cvt.u32.u64 %0, t; }"
        : "=r"(a) : "l"(p));
    return a;
}
#define CP_ASYNC16(dst, src) \
    asm volatile("cp.async.ca.shared.global [%0], [%1], 16;" :: "r"(dst), "l"(src))
#define CP_COMMIT() asm volatile("cp.async.commit_group;" ::: "memory")
#define CP_WAIT1()  asm volatile("cp.async.wait_group 1;" ::: "memory")
#define CP_WAIT0()  asm volatile("cp.async.wait_group 0;" ::: "memory")

// smem geometry (uint32 units).
// A: [66 rows][132]  (128 kpairs + pad; 132 % 32 = 4  -> frag bank = 4g+q, distinct)
// B: [64 kpairs][264] (256 n + pad;   264 % 32 = 8  -> frag bank = 8q+g, distinct)
#define A_STR 132
#define B_STR 264
#define A_U32 (66 * A_STR)               // 8712
#define B_U32 (64 * B_STR)               // 16896
#define SMEM_BYTES ((A_U32 + 2 * B_U32) * 4)   // 170016

// ---------------------------------------------------------------------------
// Prep: weight fp16 pack (vectorized, blocks 0..95) + cumsum/frame-idx (96..111)
// ---------------------------------------------------------------------------
__global__ void __launch_bounds__(512) prep_kernel(const float* __restrict__ w1,
                                                   const float* __restrict__ w2,
                                                   const int* __restrict__ dur)
{
    if (blockIdx.x < 96) {
        int idx = blockIdx.x * 512 + threadIdx.x;      // 0..49151
        int n4 = idx & 63;
        int kp = (idx >> 6) & 127;
        int t  = idx >> 13;                            // 0..5
        int tap = t % 3, conv = t / 3;
        const float* src = (conv ? w2 : w1) + (size_t)tap * 65536
                         + (size_t)(2 * kp) * 256 + n4 * 4;
        float4 lo = *(const float4*)(src);
        float4 hi = *(const float4*)(src + 256);
        uint4 o;
        o.x = pack_h2(lo.x, hi.x);
        o.y = pack_h2(lo.y, hi.y);
        o.z = pack_h2(lo.z, hi.z);
        o.w = pack_h2(lo.w, hi.w);
        *(uint4*)(g_wpk + ((size_t)(conv * 3 + tap) * 128 + kp) * 256 + n4 * 4) = o;
        return;
    }
    __shared__ int s[LL];
    int b = blockIdx.x - 96, tid = threadIdx.x;
    s[tid] = dur[b * LL + tid];
    __syncthreads();
    for (int off = 1; off < LL; off <<= 1) {
        int v = (tid >= off) ? s[tid - off] : 0;
        __syncthreads();
        s[tid] += v;
        __syncthreads();
    }
    int total = s[LL - 1];
#pragma unroll
    for (int r = 0; r < 8; r++) {
        int t = tid + r * 512;
        int lo = 0, hi = LL;
        while (lo < hi) {
            int mid = (lo + hi) >> 1;
            if (s[mid] <= t) lo = mid + 1; else hi = mid;
        }
        g_idx[b * MEL + t] = (t < total) ? min(lo, LL - 1) : -1;
    }
}

// ---------------------------------------------------------------------------
// Fused conv1d(K=3,SAME)+bias+ReLU+LN [+linear head if FINAL], fp16 MMA.
// CTA = [64 l x 256 f], 256 threads / 8 warps, warp tile 64x32.
// A resident (half2, [row][kpair]); B cp.async double-buffered in 64-kpair chunks
// (6 mainloop iters). Each conv streams HALF of the length-regulated output.
// ---------------------------------------------------------------------------
template <bool FINAL>
__global__ void __launch_bounds__(256, 1)
conv_mma_kernel(const float* __restrict__ xin,
                const float* __restrict__ bias,
                const float* __restrict__ gamma,
                const float* __restrict__ beta,
                const float* __restrict__ linw,
                const float* __restrict__ linb,
                float* __restrict__ predout,
                float* __restrict__ regout)
{
    extern __shared__ __align__(16) uint32_t smu[];
    uint32_t* sA2 = smu;
    uint32_t* sB[2] = { smu + A_U32, smu + A_U32 + B_U32 };
    const uint32_t sa_u32 = smem_u32(sA2);
    const uint32_t sb_u32[2] = { smem_u32(sB[0]), smem_u32(sB[1]) };

    const int tid  = threadIdx.x;
    const int warp = tid >> 5, lane = tid & 31;
    const int g = lane >> 2, q = lane & 3;
    const int n0 = warp * 32;
    const int b  = blockIdx.y;
    const int l0 = blockIdx.x * 64;
    const int CONV = FINAL ? 1 : 0;
    // this CTA's regulate range: 256 frames (conv1: first half of tile, conv2: second)
    const int fbase = blockIdx.x * 512 + (FINAL ? 256 : 0);

    auto stageB = [&](int it, int buf) {
        const uint32_t* src = g_wpk + ((size_t)(CONV * 3 + (it >> 1)) * 128 + (it & 1) * 64) * 256;
#pragma unroll
        for (int i = 0; i < 16; i++) {
            int idx = tid + i * 256;               // 0..4095 (16B segs)
            int c = idx >> 6, n4 = idx & 63;
            CP_ASYNC16(sb_u32[buf] + (uint32_t)(c * B_STR + n4 * 4) * 4,
                       src + (size_t)c * 256 + n4 * 4);
        }
        CP_COMMIT();
    };

    stageB(0, 0);
    if (FINAL) {
        // A from packed h1: straight cp.async rows, zero-fill OOB
        const uint32_t* h1b = g_h1pk + (size_t)b * LL * 128;
#pragma unroll
        for (int i = 0; i < 9; i++) {
            int idx = tid + i * 256;               // need 66*32 = 2112 segs
            if (idx < 66 * 32) {
                int row = idx >> 5, seg = idx & 31;
                int grow = l0 + row - 1;
                if (grow >= 0 && grow < LL)
                    CP_ASYNC16(sa_u32 + (uint32_t)(row * A_STR + seg * 4) * 4,
                               h1b + (size_t)grow * 128 + seg * 4);
                else
                    *(float4*)(sA2 + row * A_STR + seg * 4) =
                        make_float4(0.f, 0.f, 0.f, 0.f);
            }
        }
        CP_COMMIT();
    }
    stageB(1, 1);
    if (!FINAL) {
        // A from fp32 x: convert+pack, transposed store (STS.64, coalesced)
        const float* inb = xin + (size_t)b * LL * CC;
#pragma unroll 4
        for (int i = 0; i < 17; i++) {
            int idx = tid + i * 256;               // need 66*64 = 4224
            if (idx < 66 * 64) {
                int c4 = idx & 63, row = idx >> 6;
                int grow = l0 + row - 1;
                float4 v = make_float4(0.f, 0.f, 0.f, 0.f);
                if (grow >= 0 && grow < LL)
                    v = *(const float4*)(inb + (size_t)grow * CC + c4 * 4);
                uint32_t h01 = pack_h2(v.x, v.y);
                uint32_t h23 = pack_h2(v.z, v.w);
                unsigned long long dd = ((unsigned long long)h23 << 32) | h01;
                *(unsigned long long*)(sA2 + row * A_STR + c4 * 2) = dd;
            }
        }
    }

    float acc[4][4][4];
#pragma unroll
    for (int mt = 0; mt < 4; mt++)
#pragma unroll
        for (int nt = 0; nt < 4; nt++)
#pragma unroll
            for (int r = 0; r < 4; r++) acc[mt][nt][r] = 0.f;

    for (int it = 0; it < 6; it++) {
        const int ktap = it >> 1, koff = (it & 1) * 64;
        const int buf = it & 1;
        if (it < 5) CP_WAIT1(); else CP_WAIT0();
        __syncthreads();

        const uint32_t* ab = sA2 + (ktap + g) * A_STR + koff + q;
        const uint32_t* bb = sB[buf] + n0 + g;
#pragma unroll
        for (int ks = 0; ks < 8; ks++) {
            uint32_t af[4][4], bf[4][2];
#pragma unroll
            for (int mt = 0; mt < 4; mt++) {
                const uint32_t* ap = ab + mt * (16 * A_STR) + ks * 8;
                af[mt][0] = ap[0];
                af[mt][1] = ap[8 * A_STR];
                af[mt][2] = ap[4];
                af[mt][3] = ap[8 * A_STR + 4];
            }
#pragma unroll
            for (int nt = 0; nt < 4; nt++) {
                bf[nt][0] = bb[(ks * 8 + q) * B_STR + nt * 8];
                bf[nt][1] = bb[(ks * 8 + q + 4) * B_STR + nt * 8];
            }
#pragma unroll
            for (int mt = 0; mt < 4; mt++)
#pragma unroll
                for (int nt = 0; nt < 4; nt++)
                    mma_f16(acc[mt][nt], af[mt], bf[nt]);
        }
        __syncthreads();
        if (it + 2 < 6) stageB(it + 2, buf);

        // ---- interleaved length regulation: 256 frames per CTA, 64 slots/thr,
        //      11 float4 slots per iteration (6*11 = 66 >= 64) ----
        {
            int ix[11];
            float4 vv[11];
#pragma unroll
            for (int u = 0; u < 11; u++) {
                int s = it * 11 + u;
                ix[u] = -1;
                if (s < 64)
                    ix[u] = g_idx[b * MEL + fbase + ((tid + s * 256) >> 6)];
            }
#pragma unroll
            for (int u = 0; u < 11; u++) {
                vv[u] = make_float4(0.f, 0.f, 0.f, 0.f);
                if (ix[u] >= 0) {
                    int s = it * 11 + u;
                    int c4 = (tid + s * 256) & 63;
                    vv[u] = *(const float4*)(xin + ((size_t)b * LL + ix[u]) * CC + c4 * 4);
                }
            }
#pragma unroll
            for (int u = 0; u < 11; u++) {
                int s = it * 11 + u;
                if (s < 64) {
                    int j = tid + s * 256;
                    int fr = j >> 6, c4 = j & 63;
                    *(float4*)(regout + ((size_t)b * MEL + fbase + fr) * CC + c4 * 4) = vv[u];
                }
            }
        }
    }
    __syncthreads();

    // ---- epilogue: bias + ReLU + LN (fused), optional linear head ----
    float bi[8], ga[8], be[8], lw[8];
#pragma unroll
    for (int nt = 0; nt < 4; nt++)
#pragma unroll
        for (int j = 0; j < 2; j++) {
            int c = n0 + nt * 8 + 2 * q + j;
            bi[nt * 2 + j] = __ldg(bias + c);
            ga[nt * 2 + j] = __ldg(gamma + c);
            be[nt * 2 + j] = __ldg(beta + c);
            if (FINAL) lw[nt * 2 + j] = __ldg(linw + c);
        }

    float v[4][2][8];
    float2* red   = (float2*)sA2;                  // [64 rows][8 warps]
    float2* stats = red + 512;                     // [64]
    float*  dred  = (float*)sA2 + 2048;            // [64 rows][8 warps]

#pragma unroll
    for (int mt = 0; mt < 4; mt++)
#pragma unroll
        for (int h = 0; h < 2; h++) {
            float s = 0.f, s2 = 0.f;
#pragma unroll
            for (int nt = 0; nt < 4; nt++)
#pragma unroll
                for (int j = 0; j < 2; j++) {
                    float x = acc[mt][nt][h * 2 + j] + bi[nt * 2 + j];
                    x = fmaxf(x, 0.f);
                    v[mt][h][nt * 2 + j] = x;
                    s += x; s2 += x * x;
                }
            s  += __shfl_xor_sync(0xffffffffu, s, 1);
            s2 += __shfl_xor_sync(0xffffffffu, s2, 1);
            s  += __shfl_xor_sync(0xffffffffu, s, 2);
            s2 += __shfl_xor_sync(0xffffffffu, s2, 2);
            if (q == 0)
                red[(mt * 16 + g + 8 * h) * 8 + warp] = make_float2(s, s2);
        }
    __syncthreads();
    if (tid < 64) {
        float s = 0.f, s2 = 0.f;
#pragma unroll
        for (int wv = 0; wv < 8; wv++) {
            float2 p = red[tid * 8 + wv];
            s += p.x; s2 += p.y;
        }
        float mu = s * (1.f / 256.f);
        float var = s2 * (1.f / 256.f) - mu * mu;
        stats[tid] = make_float2(mu, rsqrtf(var + 1e-5f));
    }
    __syncthreads();

    if (!FINAL) {
        // store h1 as packed fp16 (conv2 consumes directly)
#pragma unroll
        for (int mt = 0; mt < 4; mt++)
#pragma unroll
            for (int h = 0; h < 2; h++) {
                int r = mt * 16 + g + 8 * h;
                float2 st = stats[r];
                uint32_t* orow = g_h1pk + ((size_t)b * LL + l0 + r) * 128 + warp * 16;
#pragma unroll
                for (int nt = 0; nt < 4; nt++) {
                    float ox = (v[mt][h][nt * 2]     - st.x) * st.y * ga[nt * 2]     + be[nt * 2];
                    float oy = (v[mt][h][nt * 2 + 1] - st.x) * st.y * ga[nt * 2 + 1] + be[nt * 2 + 1];
                    orow[nt * 4 + q] = pack_h2(ox, oy);
                }
            }
    } else {
#pragma unroll
        for (int mt = 0; mt < 4; mt++)
#pragma unroll
            for (int h = 0; h < 2; h++) {
                int r = mt * 16 + g + 8 * h;
                float2 st = stats[r];
                float d = 0.f;
#pragma unroll
                for (int p = 0; p < 8; p++)
                    d += ((v[mt][h][p] - st.x) * st.y * ga[p] + be[p]) * lw[p];
                d += __shfl_xor_sync(0xffffffffu, d, 1);
                d += __shfl_xor_sync(0xffffffffu, d, 2);
                if (q == 0) dred[r * 8 + warp] = d;
            }
        __syncthreads();
        if (tid < 64) {
            float d = 0.f;
#pragma unroll
            for (int wv = 0; wv < 8; wv++) d += dred[tid * 8 + wv];
            predout[b * LL + l0 + tid] = d + __ldg(linb);
        }
    }
}

// ---------------------------------------------------------------------------
extern "C" void kernel_launch(void* const* d_in, const int* in_sizes, int n_in,
                              void* d_out, int out_size)
{
    const float* x    = (const float*)d_in[0];
    const int*   dur  = (const int*)d_in[1];
    const float* c1w  = (const float*)d_in[2];
    const float* c1b  = (const float*)d_in[3];
    const float* ln1g = (const float*)d_in[4];
    const float* ln1b = (const float*)d_in[5];
    const float* c2w  = (const float*)d_in[6];
    const float* c2b  = (const float*)d_in[7];
    const float* ln2g = (const float*)d_in[8];
    const float* ln2b = (const float*)d_in[9];
    const float* linw = (const float*)d_in[10];
    const float* linb = (const float*)d_in[11];

    float* out  = (float*)d_out;
    float* pred = out + (size_t)BB * MEL * CC;

    cudaFuncSetAttribute(conv_mma_kernel<false>,
                         cudaFuncAttributeMaxDynamicSharedMemorySize, SMEM_BYTES);
    cudaFuncSetAttribute(conv_mma_kernel<true>,
                         cudaFuncAttributeMaxDynamicSharedMemorySize, SMEM_BYTES);

    prep_kernel<<<96 + BB, 512>>>(c1w, c2w, dur);

    dim3 cgrid(LL / 64, BB);
    conv_mma_kernel<false><<<cgrid, 256, SMEM_BYTES>>>(x, c1b, ln1g, ln1b,
                                                       nullptr, nullptr, nullptr, out);
    conv_mma_kernel<true><<<cgrid, 256, SMEM_BYTES>>>(x, c2b, ln2g, ln2b,
                                                      linw, linb, pred, out);
}

// round 10
// speedup vs baseline: 3.0608x; 1.1016x over previous
#include <cuda_runtime.h>
#include <cuda_fp16.h>
#include <cstdint>

#define BB   16
#define LL   512
#define CC   256
#define MEL  4096

// ---------------------------------------------------------------------------
// Scratch (__device__ globals — allocations are forbidden)
// ---------------------------------------------------------------------------
__device__ uint32_t g_xpk[BB * LL * 128];         // x packed half2 [b][l][kpair]
__device__ uint32_t g_h1pk[BB * LL * 128];        // h1 packed half2
__device__ int      g_idx[BB * MEL];              // per-frame token index
__device__ uint32_t g_wpk[2 * 3 * 128 * 256];     // weights packed half2 [conv][tap][kpair][n]

// ---------------------------------------------------------------------------
__device__ __forceinline__ uint32_t pack_h2(float a, float b) {
    __half2 h = __floats2half2_rn(a, b);
    return *reinterpret_cast<uint32_t*>(&h);
}
__device__ __forceinline__ void mma_f16(float* d, const uint32_t* a, const uint32_t* b) {
    asm volatile(
        "mma.sync.aligned.m16n8k16.row.col.f32.f16.f16.f32 "
        "{%0,%1,%2,%3}, {%4,%5,%6,%7}, {%8,%9}, {%0,%1,%2,%3};"
        : "+f"(d[0]), "+f"(d[1]), "+f"(d[2]), "+f"(d[3])
        : "r"(a[0]), "r"(a[1]), "r"(a[2]), "r"(a[3]), "r"(b[0]), "r"(b[1]));
}
__device__ __forceinline__ uint32_t smem_u32(const void* p) {
    uint32_t a;
    asm("{ .reg .u64 t; cvta.to.shared.u64 t, %1; cvt.u32.u64 %0, t; }"
        : "=r"(a) : "l"(p));
    return a;
}
#define CP_ASYNC16(dst, src) \
    asm volatile("cp.async.ca.shared.global [%0], [%1], 16;" :: "r"(dst), "l"(src))
#define CP_COMMIT() asm volatile("cp.async.commit_group;" ::: "memory")
#define CP_WAIT1()  asm volatile("cp.async.wait_group 1;" ::: "memory")
#define CP_WAIT0()  asm volatile("cp.async.wait_group 0;" ::: "memory")

// smem geometry (uint32 units).
#define A_STR 132
#define B_STR 264
#define A_U32 (66 * A_STR)               // 8712
#define B_U32 (64 * B_STR)               // 16896
#define IDX_OFF (A_U32 + 2 * B_U32)      // 42504
#define SMEM_BYTES ((IDX_OFF + 256) * 4) // 171040

// ---------------------------------------------------------------------------
// Prep: x fp16 pack (blocks 0..511) + weight pack (512..607) + cumsum (608..623)
// ---------------------------------------------------------------------------
__global__ void __launch_bounds__(512) prep_kernel(const float* __restrict__ x,
                                                   const float* __restrict__ w1,
                                                   const float* __restrict__ w2,
                                                   const int* __restrict__ dur)
{
    if (blockIdx.x < 512) {
        int idx = blockIdx.x * 512 + threadIdx.x;      // 0..262143 uint4 slots
        int row = idx >> 5, seg = idx & 31;
        const float* src = x + (size_t)row * CC + seg * 8;
        float4 a  = *(const float4*)(src);
        float4 b4 = *(const float4*)(src + 4);
        uint4 o;
        o.x = pack_h2(a.x, a.y);
        o.y = pack_h2(a.z, a.w);
        o.z = pack_h2(b4.x, b4.y);
        o.w = pack_h2(b4.z, b4.w);
        ((uint4*)g_xpk)[idx] = o;
        return;
    }
    if (blockIdx.x < 608) {
        int idx = (blockIdx.x - 512) * 512 + threadIdx.x;  // 0..49151
        int n4 = idx & 63;
        int kp = (idx >> 6) & 127;
        int t  = idx >> 13;                            // 0..5
        int tap = t % 3, conv = t / 3;
        const float* src = (conv ? w2 : w1) + (size_t)tap * 65536
                         + (size_t)(2 * kp) * 256 + n4 * 4;
        float4 lo = *(const float4*)(src);
        float4 hi = *(const float4*)(src + 256);
        uint4 o;
        o.x = pack_h2(lo.x, hi.x);
        o.y = pack_h2(lo.y, hi.y);
        o.z = pack_h2(lo.z, hi.z);
        o.w = pack_h2(lo.w, hi.w);
        *(uint4*)(g_wpk + ((size_t)(conv * 3 + tap) * 128 + kp) * 256 + n4 * 4) = o;
        return;
    }
    // cumsum + frame->token idx, warp-shuffle scan
    __shared__ int s[LL];
    __shared__ int wsum[16];
    int b = blockIdx.x - 608, tid = threadIdx.x;
    int lane = tid & 31, wid = tid >> 5;
    int v = dur[b * LL + tid];
#pragma unroll
    for (int off = 1; off < 32; off <<= 1) {
        int t = __shfl_up_sync(0xffffffffu, v, off);
        if (lane >= off) v += t;
    }
    if (lane == 31) wsum[wid] = v;
    __syncthreads();
    if (wid == 0 && lane < 16) {
        int w = wsum[lane];
#pragma unroll
        for (int off = 1; off < 16; off <<= 1) {
            int t = __shfl_up_sync(0xffffu, w, off);
            if (lane >= off) w += t;
        }
        wsum[lane] = w;
    }
    __syncthreads();
    if (wid > 0) v += wsum[wid - 1];
    s[tid] = v;
    __syncthreads();
    int total = s[LL - 1];
#pragma unroll
    for (int r = 0; r < 8; r++) {
        int t = tid + r * 512;
        int lo = 0, hi = LL;
        while (lo < hi) {
            int mid = (lo + hi) >> 1;
            if (s[mid] <= t) lo = mid + 1; else hi = mid;
        }
        g_idx[b * MEL + t] = (t < total) ? min(lo, LL - 1) : -1;
    }
}

// ---------------------------------------------------------------------------
// Fused conv1d(K=3,SAME)+bias+ReLU+LN [+linear head if FINAL], fp16 MMA.
// CTA = [64 l x 256 f], 256 threads / 8 warps, warp tile 64x32.
// A resident via cp.async (packed fp16 source); B double-buffered (64-kpair
// chunks, 6 iters). Each conv streams half the regulate output, with gather
// loads issued BEFORE the MMA block (latency hidden under MMA).
// ---------------------------------------------------------------------------
template <bool FINAL>
__global__ void __launch_bounds__(256, 1)
conv_mma_kernel(const float* __restrict__ xin,
                const float* __restrict__ bias,
                const float* __restrict__ gamma,
                const float* __restrict__ beta,
                const float* __restrict__ linw,
                const float* __restrict__ linb,
                float* __restrict__ predout,
                float* __restrict__ regout)
{
    extern __shared__ __align__(16) uint32_t smu[];
    uint32_t* sA2 = smu;
    uint32_t* sB[2] = { smu + A_U32, smu + A_U32 + B_U32 };
    int* sIdx = (int*)(smu + IDX_OFF);
    const uint32_t sa_u32 = smem_u32(sA2);
    const uint32_t sb_u32[2] = { smem_u32(sB[0]), smem_u32(sB[1]) };
    const uint32_t sidx_u32 = smem_u32(sIdx);

    const int tid  = threadIdx.x;
    const int warp = tid >> 5, lane = tid & 31;
    const int g = lane >> 2, q = lane & 3;
    const int n0 = warp * 32;
    const int b  = blockIdx.y;
    const int l0 = blockIdx.x * 64;
    const int CONV = FINAL ? 1 : 0;
    const int fbase = blockIdx.x * 512 + (FINAL ? 256 : 0);

    auto stageB = [&](int it, int buf) {
        const uint32_t* src = g_wpk + ((size_t)(CONV * 3 + (it >> 1)) * 128 + (it & 1) * 64) * 256;
#pragma unroll
        for (int i = 0; i < 16; i++) {
            int idx = tid + i * 256;
            int c = idx >> 6, n4 = idx & 63;
            CP_ASYNC16(sb_u32[buf] + (uint32_t)(c * B_STR + n4 * 4) * 4,
                       src + (size_t)c * 256 + n4 * 4);
        }
        CP_COMMIT();
    };

    stageB(0, 0);
    // ---- A (packed fp16) + idx slice, one commit group ----
    {
        const uint32_t* apk = (FINAL ? g_h1pk : g_xpk) + (size_t)b * LL * 128;
#pragma unroll
        for (int i = 0; i < 9; i++) {
            int idx = tid + i * 256;               // need 66*32 = 2112 segs
            if (idx < 66 * 32) {
                int row = idx >> 5, seg = idx & 31;
                int grow = l0 + row - 1;
                if (grow >= 0 && grow < LL)
                    CP_ASYNC16(sa_u32 + (uint32_t)(row * A_STR + seg * 4) * 4,
                               apk + (size_t)grow * 128 + seg * 4);
                else
                    *(float4*)(sA2 + row * A_STR + seg * 4) =
                        make_float4(0.f, 0.f, 0.f, 0.f);
            }
        }
        if (tid < 64)
            CP_ASYNC16(sidx_u32 + tid * 16, g_idx + b * MEL + fbase + tid * 4);
        CP_COMMIT();
    }
    stageB(1, 1);

    float acc[4][4][4];
#pragma unroll
    for (int mt = 0; mt < 4; mt++)
#pragma unroll
        for (int nt = 0; nt < 4; nt++)
#pragma unroll
            for (int r = 0; r < 4; r++) acc[mt][nt][r] = 0.f;

    for (int it = 0; it < 6; it++) {
        const int ktap = it >> 1, koff = (it & 1) * 64;
        const int buf = it & 1;
        if (it < 5) CP_WAIT1(); else CP_WAIT0();
        __syncthreads();

        // ---- regulate: issue gather loads now; latency hides under MMA ----
        int ix[11];
        float4 vv[11];
#pragma unroll
        for (int u = 0; u < 11; u++) {
            int s = it * 11 + u;
            ix[u] = (s < 64) ? sIdx[(tid + s * 256) >> 6] : -1;
        }
#pragma unroll
        for (int u = 0; u < 11; u++) {
            vv[u] = make_float4(0.f, 0.f, 0.f, 0.f);
            if (ix[u] >= 0) {
                int s = it * 11 + u;
                int c4 = (tid + s * 256) & 63;
                vv[u] = *(const float4*)(xin + ((size_t)b * LL + ix[u]) * CC + c4 * 4);
            }
        }

        const uint32_t* ab = sA2 + (ktap + g) * A_STR + koff + q;
        const uint32_t* bb = sB[buf] + n0 + g;
#pragma unroll
        for (int ks = 0; ks < 8; ks++) {
            uint32_t af[4][4], bf[4][2];
#pragma unroll
            for (int mt = 0; mt < 4; mt++) {
                const uint32_t* ap = ab + mt * (16 * A_STR) + ks * 8;
                af[mt][0] = ap[0];
                af[mt][1] = ap[8 * A_STR];
                af[mt][2] = ap[4];
                af[mt][3] = ap[8 * A_STR + 4];
            }
#pragma unroll
            for (int nt = 0; nt < 4; nt++) {
                bf[nt][0] = bb[(ks * 8 + q) * B_STR + nt * 8];
                bf[nt][1] = bb[(ks * 8 + q + 4) * B_STR + nt * 8];
            }
#pragma unroll
            for (int mt = 0; mt < 4; mt++)
#pragma unroll
                for (int nt = 0; nt < 4; nt++)
                    mma_f16(acc[mt][nt], af[mt], bf[nt]);
        }
        __syncthreads();
        if (it + 2 < 6) stageB(it + 2, buf);

        // ---- regulate stores ----
#pragma unroll
        for (int u = 0; u < 11; u++) {
            int s = it * 11 + u;
            if (s < 64) {
                int j = tid + s * 256;
                int fr = j >> 6, c4 = j & 63;
                *(float4*)(regout + ((size_t)b * MEL + fbase + fr) * CC + c4 * 4) = vv[u];
            }
        }
    }
    __syncthreads();

    // ---- epilogue: bias + ReLU + LN (fused), optional linear head ----
    float bi[8], ga[8], be[8], lw[8];
#pragma unroll
    for (int nt = 0; nt < 4; nt++)
#pragma unroll
        for (int j = 0; j < 2; j++) {
            int c = n0 + nt * 8 + 2 * q + j;
            bi[nt * 2 + j] = __ldg(bias + c);
            ga[nt * 2 + j] = __ldg(gamma + c);
            be[nt * 2 + j] = __ldg(beta + c);
            if (FINAL) lw[nt * 2 + j] = __ldg(linw + c);
        }

    float v[4][2][8];
    float2* red   = (float2*)sA2;                  // [64 rows][8 warps]
    float2* stats = red + 512;                     // [64]
    float*  dred  = (float*)sA2 + 2048;            // [64 rows][8 warps]

#pragma unroll
    for (int mt = 0; mt < 4; mt++)
#pragma unroll
        for (int h = 0; h < 2; h++) {
            float s = 0.f, s2 = 0.f;
#pragma unroll
            for (int nt = 0; nt < 4; nt++)
#pragma unroll
                for (int j = 0; j < 2; j++) {
                    float x = acc[mt][nt][h * 2 + j] + bi[nt * 2 + j];
                    x = fmaxf(x, 0.f);
                    v[mt][h][nt * 2 + j] = x;
                    s += x; s2 += x * x;
                }
            s  += __shfl_xor_sync(0xffffffffu, s, 1);
            s2 += __shfl_xor_sync(0xffffffffu, s2, 1);
            s  += __shfl_xor_sync(0xffffffffu, s, 2);
            s2 += __shfl_xor_sync(0xffffffffu, s2, 2);
            if (q == 0)
                red[(mt * 16 + g + 8 * h) * 8 + warp] = make_float2(s, s2);
        }
    __syncthreads();
    if (tid < 64) {
        float s = 0.f, s2 = 0.f;
#pragma unroll
        for (int wv = 0; wv < 8; wv++) {
            float2 p = red[tid * 8 + wv];
            s += p.x; s2 += p.y;
        }
        float mu = s * (1.f / 256.f);
        float var = s2 * (1.f / 256.f) - mu * mu;
        stats[tid] = make_float2(mu, rsqrtf(var + 1e-5f));
    }
    __syncthreads();

    if (!FINAL) {
#pragma unroll
        for (int mt = 0; mt < 4; mt++)
#pragma unroll
            for (int h = 0; h < 2; h++) {
                int r = mt * 16 + g + 8 * h;
                float2 st = stats[r];
                uint32_t* orow = g_h1pk + ((size_t)b * LL + l0 + r) * 128 + warp * 16;
#pragma unroll
                for (int nt = 0; nt < 4; nt++) {
                    float ox = (v[mt][h][nt * 2]     - st.x) * st.y * ga[nt * 2]     + be[nt * 2];
                    float oy = (v[mt][h][nt * 2 + 1] - st.x) * st.y * ga[nt * 2 + 1] + be[nt * 2 + 1];
                    orow[nt * 4 + q] = pack_h2(ox, oy);
                }
            }
    } else {
#pragma unroll
        for (int mt = 0; mt < 4; mt++)
#pragma unroll
            for (int h = 0; h < 2; h++) {
                int r = mt * 16 + g + 8 * h;
                float2 st = stats[r];
                float d = 0.f;
#pragma unroll
                for (int p = 0; p < 8; p++)
                    d += ((v[mt][h][p] - st.x) * st.y * ga[p] + be[p]) * lw[p];
                d += __shfl_xor_sync(0xffffffffu, d, 1);
                d += __shfl_xor_sync(0xffffffffu, d, 2);
                if (q == 0) dred[r * 8 + warp] = d;
            }
        __syncthreads();
        if (tid < 64) {
            float d = 0.f;
#pragma unroll
            for (int wv = 0; wv < 8; wv++) d += dred[tid * 8 + wv];
            predout[b * LL + l0 + tid] = d + __ldg(linb);
        }
    }
}

// ---------------------------------------------------------------------------
extern "C" void kernel_launch(void* const* d_in, const int* in_sizes, int n_in,
                              void* d_out, int out_size)
{
    const float* x    = (const float*)d_in[0];
    const int*   dur  = (const int*)d_in[1];
    const float* c1w  = (const float*)d_in[2];
    const float* c1b  = (const float*)d_in[3];
    const float* ln1g = (const float*)d_in[4];
    const float* ln1b = (const float*)d_in[5];
    const float* c2w  = (const float*)d_in[6];
    const float* c2b  = (const float*)d_in[7];
    const float* ln2g = (const float*)d_in[8];
    const float* ln2b = (const float*)d_in[9];
    const float* linw = (const float*)d_in[10];
    const float* linb = (const float*)d_in[11];

    float* out  = (float*)d_out;
    float* pred = out + (size_t)BB * MEL * CC;

    cudaFuncSetAttribute(conv_mma_kernel<false>,
                         cudaFuncAttributeMaxDynamicSharedMemorySize, SMEM_BYTES);
    cudaFuncSetAttribute(conv_mma_kernel<true>,
                         cudaFuncAttributeMaxDynamicSharedMemorySize, SMEM_BYTES);

    prep_kernel<<<512 + 96 + BB, 512>>>(x, c1w, c2w, dur);

    dim3 cgrid(LL / 64, BB);
    conv_mma_kernel<false><<<cgrid, 256, SMEM_BYTES>>>(x, c1b, ln1g, ln1b,
                                                       nullptr, nullptr, nullptr, out);
    conv_mma_kernel<true><<<cgrid, 256, SMEM_BYTES>>>(x, c2b, ln2g, ln2b,
                                                      linw, linb, pred, out);
}

// round 11
// speedup vs baseline: 3.3022x; 1.0789x over previous
#include <cuda_runtime.h>
#include <cuda_fp16.h>
#include <cstdint>

#define BB   16
#define LL   512
#define CC   256
#define MEL  4096

// ---------------------------------------------------------------------------
// Scratch (__device__ globals — allocations are forbidden)
// ---------------------------------------------------------------------------
__device__ uint32_t g_xpk[BB * LL * 128];         // x packed half2 [b][l][kpair]
__device__ uint32_t g_h1pk[BB * LL * 128];        // h1 packed half2
__device__ int      g_idx[BB * MEL];              // per-frame token index
__device__ uint32_t g_wpk[2 * 3 * 128 * 256];     // weights packed half2 [conv][tap][kpair][n]

// ---------------------------------------------------------------------------
__device__ __forceinline__ uint32_t pack_h2(float a, float b) {
    __half2 h = __floats2half2_rn(a, b);
    return *reinterpret_cast<uint32_t*>(&h);
}
__device__ __forceinline__ void mma_f16(float* d, const uint32_t* a, const uint32_t* b) {
    asm volatile(
        "mma.sync.aligned.m16n8k16.row.col.f32.f16.f16.f32 "
        "{%0,%1,%2,%3}, {%4,%5,%6,%7}, {%8,%9}, {%0,%1,%2,%3};"
        : "+f"(d[0]), "+f"(d[1]), "+f"(d[2]), "+f"(d[3])
        : "r"(a[0]), "r"(a[1]), "r"(a[2]), "r"(a[3]), "r"(b[0]), "r"(b[1]));
}
__device__ __forceinline__ uint32_t smem_u32(const void* p) {
    uint32_t a;
    asm("{ .reg .u64 t; cvta.to.shared.u64 t, %1; cvt.u32.u64 %0, t; }"
        : "=r"(a) : "l"(p));
    return a;
}
#define CP_ASYNC16(dst, src) \
    asm volatile("cp.async.ca.shared.global [%0], [%1], 16;" :: "r"(dst), "l"(src))
#define CP_COMMIT() asm volatile("cp.async.commit_group;" ::: "memory")
#define CP_WAIT2()  asm volatile("cp.async.wait_group 2;" ::: "memory")
#define CP_WAIT1()  asm volatile("cp.async.wait_group 1;" ::: "memory")
#define CP_WAIT0()  asm volatile("cp.async.wait_group 0;" ::: "memory")

// smem geometry (uint32 units).
#define A_STR 132
#define B_STR 264
#define A_U32 (66 * A_STR)               // 8712
#define B32_U32 (32 * B_STR)             // 8448 (one 32-kpair chunk)
#define IDX_OFF (A_U32 + 4 * B32_U32)    // 42504
#define SMEM_BYTES ((IDX_OFF + 256) * 4) // 171040

// ---------------------------------------------------------------------------
// Prep: x pack (blocks 0..255, 2 slots/thread), w pack (256..303), cumsum (304..319)
// ---------------------------------------------------------------------------
__global__ void __launch_bounds__(512) prep_kernel(const float* __restrict__ x,
                                                   const float* __restrict__ w1,
                                                   const float* __restrict__ w2,
                                                   const int* __restrict__ dur)
{
    if (blockIdx.x < 256) {
        int j = blockIdx.x * 512 + threadIdx.x;        // slots j, j+131072
        int j2 = j + 131072;
        const float* s0 = x + (size_t)(j >> 5) * CC + (j & 31) * 8;
        const float* s1 = x + (size_t)(j2 >> 5) * CC + (j2 & 31) * 8;
        float4 a0 = *(const float4*)(s0);
        float4 b0 = *(const float4*)(s0 + 4);
        float4 a1 = *(const float4*)(s1);
        float4 b1 = *(const float4*)(s1 + 4);
        uint4 o0, o1;
        o0.x = pack_h2(a0.x, a0.y); o0.y = pack_h2(a0.z, a0.w);
        o0.z = pack_h2(b0.x, b0.y); o0.w = pack_h2(b0.z, b0.w);
        o1.x = pack_h2(a1.x, a1.y); o1.y = pack_h2(a1.z, a1.w);
        o1.z = pack_h2(b1.x, b1.y); o1.w = pack_h2(b1.z, b1.w);
        ((uint4*)g_xpk)[j]  = o0;
        ((uint4*)g_xpk)[j2] = o1;
        return;
    }
    if (blockIdx.x < 304) {
        int idx = (blockIdx.x - 256) * 512 + threadIdx.x;  // 0..24575; +24576
#pragma unroll
        for (int r = 0; r < 2; r++) {
            int id = idx + r * 24576;
            int n4 = id & 63;
            int kp = (id >> 6) & 127;
            int t  = id >> 13;                         // 0..5
            int tap = t % 3, conv = t / 3;
            const float* src = (conv ? w2 : w1) + (size_t)tap * 65536
                             + (size_t)(2 * kp) * 256 + n4 * 4;
            float4 lo = *(const float4*)(src);
            float4 hi = *(const float4*)(src + 256);
            uint4 o;
            o.x = pack_h2(lo.x, hi.x);
            o.y = pack_h2(lo.y, hi.y);
            o.z = pack_h2(lo.z, hi.z);
            o.w = pack_h2(lo.w, hi.w);
            *(uint4*)(g_wpk + ((size_t)(conv * 3 + tap) * 128 + kp) * 256 + n4 * 4) = o;
        }
        return;
    }
    // cumsum + frame->token idx, warp-shuffle scan
    __shared__ int s[LL];
    __shared__ int wsum[16];
    int b = blockIdx.x - 304, tid = threadIdx.x;
    int lane = tid & 31, wid = tid >> 5;
    int v = dur[b * LL + tid];
#pragma unroll
    for (int off = 1; off < 32; off <<= 1) {
        int t = __shfl_up_sync(0xffffffffu, v, off);
        if (lane >= off) v += t;
    }
    if (lane == 31) wsum[wid] = v;
    __syncthreads();
    if (wid == 0 && lane < 16) {
        int w = wsum[lane];
#pragma unroll
        for (int off = 1; off < 16; off <<= 1) {
            int t = __shfl_up_sync(0xffffu, w, off);
            if (lane >= off) w += t;
        }
        wsum[lane] = w;
    }
    __syncthreads();
    if (wid > 0) v += wsum[wid - 1];
    s[tid] = v;
    __syncthreads();
    int total = s[LL - 1];
#pragma unroll
    for (int r = 0; r < 8; r++) {
        int t = tid + r * 512;
        int lo = 0, hi = LL;
        while (lo < hi) {
            int mid = (lo + hi) >> 1;
            if (s[mid] <= t) lo = mid + 1; else hi = mid;
        }
        g_idx[b * MEL + t] = (t < total) ? min(lo, LL - 1) : -1;
    }
}

// ---------------------------------------------------------------------------
// Fused conv1d(K=3,SAME)+bias+ReLU+LN [+linear head if FINAL], fp16 MMA.
// CTA = [64 l x 256 f], 256 threads / 8 warps, warp tile 64x32.
// A resident (packed fp16 via cp.async); B in a 4-buffer, 32-kpair, 12-iter
// cp.async pipeline (3 chunks ahead, ONE barrier per iter). Each conv streams
// half the regulate output; gathers issued before MMA to hide latency.
// ---------------------------------------------------------------------------
template <bool FINAL>
__global__ void __launch_bounds__(256, 1)
conv_mma_kernel(const float* __restrict__ xin,
                const float* __restrict__ bias,
                const float* __restrict__ gamma,
                const float* __restrict__ beta,
                const float* __restrict__ linw,
                const float* __restrict__ linb,
                float* __restrict__ predout,
                float* __restrict__ regout)
{
    extern __shared__ __align__(16) uint32_t smu[];
    uint32_t* sA2 = smu;
    int* sIdx = (int*)(smu + IDX_OFF);
    const uint32_t sa_u32 = smem_u32(sA2);
    const uint32_t sb_base = sa_u32 + A_U32 * 4;
    const uint32_t sidx_u32 = smem_u32(sIdx);

    const int tid  = threadIdx.x;
    const int warp = tid >> 5, lane = tid & 31;
    const int g = lane >> 2, q = lane & 3;
    const int n0 = warp * 32;
    const int b  = blockIdx.y;
    const int l0 = blockIdx.x * 64;
    const int CONV = FINAL ? 1 : 0;
    const int fbase = blockIdx.x * 512 + (FINAL ? 256 : 0);

    // stage one 32-kpair chunk ck (0..11) into buffer ck&3
    auto stageB = [&](int ck) {
        const int buf = ck & 3;
        const uint32_t* src = g_wpk + ((size_t)(CONV * 3 + (ck >> 2)) * 128 + (ck & 3) * 32) * 256;
        const uint32_t bdst = sb_base + (uint32_t)buf * B32_U32 * 4;
#pragma unroll
        for (int i = 0; i < 8; i++) {
            int idx = tid + i * 256;               // 0..2047 16B segs
            int c = idx >> 6, n4 = idx & 63;
            CP_ASYNC16(bdst + (uint32_t)(c * B_STR + n4 * 4) * 4,
                       src + (size_t)c * 256 + n4 * 4);
        }
        CP_COMMIT();
    };

    stageB(0);
    // ---- A (packed fp16) + idx slice, one commit group ----
    {
        const uint32_t* apk = (FINAL ? g_h1pk : g_xpk) + (size_t)b * LL * 128;
#pragma unroll
        for (int i = 0; i < 9; i++) {
            int idx = tid + i * 256;               // need 66*32 = 2112 segs
            if (idx < 66 * 32) {
                int row = idx >> 5, seg = idx & 31;
                int grow = l0 + row - 1;
                if (grow >= 0 && grow < LL)
                    CP_ASYNC16(sa_u32 + (uint32_t)(row * A_STR + seg * 4) * 4,
                               apk + (size_t)grow * 128 + seg * 4);
                else
                    *(float4*)(sA2 + row * A_STR + seg * 4) =
                        make_float4(0.f, 0.f, 0.f, 0.f);
            }
        }
        if (tid < 64)
            CP_ASYNC16(sidx_u32 + tid * 16, g_idx + b * MEL + fbase + tid * 4);
        CP_COMMIT();
    }
    stageB(1);
    stageB(2);

    float acc[4][4][4];
#pragma unroll
    for (int mt = 0; mt < 4; mt++)
#pragma unroll
        for (int nt = 0; nt < 4; nt++)
#pragma unroll
            for (int r = 0; r < 4; r++) acc[mt][nt][r] = 0.f;

    for (int it = 0; it < 12; it++) {
        const int ktap = it >> 2, koff = (it & 3) * 32;
        if (it <= 9) CP_WAIT2();
        else if (it == 10) CP_WAIT1();
        else CP_WAIT0();
        __syncthreads();
        if (it + 3 < 12) stageB(it + 3);

        // ---- regulate: issue gather loads now; latency hides under MMA ----
        int ix[6];
        float4 vv[6];
#pragma unroll
        for (int u = 0; u < 6; u++) {
            int s = it * 6 + u;
            ix[u] = (s < 64) ? sIdx[(tid + s * 256) >> 6] : -1;
        }
#pragma unroll
        for (int u = 0; u < 6; u++) {
            vv[u] = make_float4(0.f, 0.f, 0.f, 0.f);
            if (ix[u] >= 0) {
                int s = it * 6 + u;
                int c4 = (tid + s * 256) & 63;
                vv[u] = *(const float4*)(xin + ((size_t)b * LL + ix[u]) * CC + c4 * 4);
            }
        }

        const uint32_t* ab = sA2 + (ktap + g) * A_STR + koff + q;
        const uint32_t* bb = (uint32_t*)(smu + A_U32 + (it & 3) * B32_U32) + n0 + g;
#pragma unroll
        for (int ks = 0; ks < 4; ks++) {
            uint32_t af[4][4], bf[4][2];
#pragma unroll
            for (int mt = 0; mt < 4; mt++) {
                const uint32_t* ap = ab + mt * (16 * A_STR) + ks * 8;
                af[mt][0] = ap[0];
                af[mt][1] = ap[8 * A_STR];
                af[mt][2] = ap[4];
                af[mt][3] = ap[8 * A_STR + 4];
            }
#pragma unroll
            for (int nt = 0; nt < 4; nt++) {
                bf[nt][0] = bb[(ks * 8 + q) * B_STR + nt * 8];
                bf[nt][1] = bb[(ks * 8 + q + 4) * B_STR + nt * 8];
            }
#pragma unroll
            for (int mt = 0; mt < 4; mt++)
#pragma unroll
                for (int nt = 0; nt < 4; nt++)
                    mma_f16(acc[mt][nt], af[mt], bf[nt]);
        }

        // ---- regulate stores ----
#pragma unroll
        for (int u = 0; u < 6; u++) {
            int s = it * 6 + u;
            if (s < 64) {
                int j = tid + s * 256;
                int fr = j >> 6, c4 = j & 63;
                *(float4*)(regout + ((size_t)b * MEL + fbase + fr) * CC + c4 * 4) = vv[u];
            }
        }
    }
    __syncthreads();

    // ---- epilogue: bias + ReLU + LN (fused), optional linear head ----
    float bi[8], ga[8], be[8], lw[8];
#pragma unroll
    for (int nt = 0; nt < 4; nt++)
#pragma unroll
        for (int j = 0; j < 2; j++) {
            int c = n0 + nt * 8 + 2 * q + j;
            bi[nt * 2 + j] = __ldg(bias + c);
            ga[nt * 2 + j] = __ldg(gamma + c);
            be[nt * 2 + j] = __ldg(beta + c);
            if (FINAL) lw[nt * 2 + j] = __ldg(linw + c);
        }

    float v[4][2][8];
    float2* red   = (float2*)sA2;                  // [64 rows][8 warps]
    float2* stats = red + 512;                     // [64]
    float*  dred  = (float*)sA2 + 2048;            // [64 rows][8 warps]

#pragma unroll
    for (int mt = 0; mt < 4; mt++)
#pragma unroll
        for (int h = 0; h < 2; h++) {
            float s = 0.f, s2 = 0.f;
#pragma unroll
            for (int nt = 0; nt < 4; nt++)
#pragma unroll
                for (int j = 0; j < 2; j++) {
                    float x = acc[mt][nt][h * 2 + j] + bi[nt * 2 + j];
                    x = fmaxf(x, 0.f);
                    v[mt][h][nt * 2 + j] = x;
                    s += x; s2 += x * x;
                }
            s  += __shfl_xor_sync(0xffffffffu, s, 1);
            s2 += __shfl_xor_sync(0xffffffffu, s2, 1);
            s  += __shfl_xor_sync(0xffffffffu, s, 2);
            s2 += __shfl_xor_sync(0xffffffffu, s2, 2);
            if (q == 0)
                red[(mt * 16 + g + 8 * h) * 8 + warp] = make_float2(s, s2);
        }
    __syncthreads();
    if (tid < 64) {
        float s = 0.f, s2 = 0.f;
#pragma unroll
        for (int wv = 0; wv < 8; wv++) {
            float2 p = red[tid * 8 + wv];
            s += p.x; s2 += p.y;
        }
        float mu = s * (1.f / 256.f);
        float var = s2 * (1.f / 256.f) - mu * mu;
        stats[tid] = make_float2(mu, rsqrtf(var + 1e-5f));
    }
    __syncthreads();

    if (!FINAL) {
#pragma unroll
        for (int mt = 0; mt < 4; mt++)
#pragma unroll
            for (int h = 0; h < 2; h++) {
                int r = mt * 16 + g + 8 * h;
                float2 st = stats[r];
                uint32_t* orow = g_h1pk + ((size_t)b * LL + l0 + r) * 128 + warp * 16;
#pragma unroll
                for (int nt = 0; nt < 4; nt++) {
                    float ox = (v[mt][h][nt * 2]     - st.x) * st.y * ga[nt * 2]     + be[nt * 2];
                    float oy = (v[mt][h][nt * 2 + 1] - st.x) * st.y * ga[nt * 2 + 1] + be[nt * 2 + 1];
                    orow[nt * 4 + q] = pack_h2(ox, oy);
                }
            }
    } else {
#pragma unroll
        for (int mt = 0; mt < 4; mt++)
#pragma unroll
            for (int h = 0; h < 2; h++) {
                int r = mt * 16 + g + 8 * h;
                float2 st = stats[r];
                float d = 0.f;
#pragma unroll
                for (int p = 0; p < 8; p++)
                    d += ((v[mt][h][p] - st.x) * st.y * ga[p] + be[p]) * lw[p];
                d += __shfl_xor_sync(0xffffffffu, d, 1);
                d += __shfl_xor_sync(0xffffffffu, d, 2);
                if (q == 0) dred[r * 8 + warp] = d;
            }
        __syncthreads();
        if (tid < 64) {
            float d = 0.f;
#pragma unroll
            for (int wv = 0; wv < 8; wv++) d += dred[tid * 8 + wv];
            predout[b * LL + l0 + tid] = d + __ldg(linb);
        }
    }
}

// ---------------------------------------------------------------------------
extern "C" void kernel_launch(void* const* d_in, const int* in_sizes, int n_in,
                              void* d_out, int out_size)
{
    const float* x    = (const float*)d_in[0];
    const int*   dur  = (const int*)d_in[1];
    const float* c1w  = (const float*)d_in[2];
    const float* c1b  = (const float*)d_in[3];
    const float* ln1g = (const float*)d_in[4];
    const float* ln1b = (const float*)d_in[5];
    const float* c2w  = (const float*)d_in[6];
    const float* c2b  = (const float*)d_in[7];
    const float* ln2g = (const float*)d_in[8];
    const float* ln2b = (const float*)d_in[9];
    const float* linw = (const float*)d_in[10];
    const float* linb = (const float*)d_in[11];

    float* out  = (float*)d_out;
    float* pred = out + (size_t)BB * MEL * CC;

    cudaFuncSetAttribute(conv_mma_kernel<false>,
                         cudaFuncAttributeMaxDynamicSharedMemorySize, SMEM_BYTES);
    cudaFuncSetAttribute(conv_mma_kernel<true>,
                         cudaFuncAttributeMaxDynamicSharedMemorySize, SMEM_BYTES);

    prep_kernel<<<256 + 48 + BB, 512>>>(x, c1w, c2w, dur);

    dim3 cgrid(LL / 64, BB);
    conv_mma_kernel<false><<<cgrid, 256, SMEM_BYTES>>>(x, c1b, ln1g, ln1b,
                                                       nullptr, nullptr, nullptr, out);
    conv_mma_kernel<true><<<cgrid, 256, SMEM_BYTES>>>(x, c2b, ln2g, ln2b,
                                                      linw, linb, pred, out);
}